// round 2
// baseline (speedup 1.0000x reference)
#include <cuda_runtime.h>
#include <math.h>

#define B1N 48
#define B2N 48
#define RN 36
#define LN 30
#define DN 1024
#define HN 4

// ---------------- scratch (static __device__, no allocs) ----------------
__device__ float g_k1[B1N*RN*DN];          // v1 @ w_img^T   (1728 x 1024)
__device__ float g_k2[B2N*LN*DN];          // v2 @ w_txt^T   (1440 x 1024)
__device__ float g_M1[B1N*RN*DN];          // v1 @ w1b^T     (1728 x 1024)
__device__ float g_M2[B2N*LN*DN];          // v2 @ w1a^T     (1440 x 1024)
__device__ float g_S [B2N*LN * B1N*RN];    // scores  S'[b*30+l][a*36+r] (scaled)
__device__ float g_G [B2N*LN * B1N*RN];    // gram    G'[b*30+l][a*36+r] = v2.v1
__device__ float g_Gram1[B1N*RN*RN];       // per-a v1 gram
__device__ float g_Gram2[B2N*LN*LN];       // per-b v2 gram

// ---------------- generic NT SGEMM: C[m,n] = alpha * sum_k A[m,k]*B[n,k] ----------------
__global__ __launch_bounds__(256, 2) void sgemm_nt(
    const float* __restrict__ A, const float* __restrict__ B,
    float* __restrict__ C, int M, int N, int K, float alpha)
{
    __shared__ float As[16][132];
    __shared__ float Bs[16][132];
    const int tid = threadIdx.x;
    const int tx = tid & 15, ty = tid >> 4;
    const int rowBase = blockIdx.y * 128;
    const int colBase = blockIdx.x * 128;

    float acc[8][8];
#pragma unroll
    for (int i = 0; i < 8; i++)
#pragma unroll
        for (int j = 0; j < 8; j++) acc[i][j] = 0.f;

    for (int kt = 0; kt < K; kt += 16) {
#pragma unroll
        for (int i = 0; i < 2; i++) {
            int lin = tid + i * 256;          // 0..511
            int row = lin >> 2;               // 0..127
            int c4  = (lin & 3) * 4;          // 0,4,8,12
            float4 av = make_float4(0.f, 0.f, 0.f, 0.f);
            if (rowBase + row < M)
                av = *(const float4*)&A[(size_t)(rowBase + row) * K + kt + c4];
            As[c4 + 0][row] = av.x; As[c4 + 1][row] = av.y;
            As[c4 + 2][row] = av.z; As[c4 + 3][row] = av.w;
            float4 bv = make_float4(0.f, 0.f, 0.f, 0.f);
            if (colBase + row < N)
                bv = *(const float4*)&B[(size_t)(colBase + row) * K + kt + c4];
            Bs[c4 + 0][row] = bv.x; Bs[c4 + 1][row] = bv.y;
            Bs[c4 + 2][row] = bv.z; Bs[c4 + 3][row] = bv.w;
        }
        __syncthreads();
#pragma unroll
        for (int kk = 0; kk < 16; kk++) {
            float4 a0 = *(const float4*)&As[kk][ty * 8];
            float4 a1 = *(const float4*)&As[kk][ty * 8 + 4];
            float4 b0 = *(const float4*)&Bs[kk][tx * 8];
            float4 b1 = *(const float4*)&Bs[kk][tx * 8 + 4];
            float af[8] = {a0.x, a0.y, a0.z, a0.w, a1.x, a1.y, a1.z, a1.w};
            float bf[8] = {b0.x, b0.y, b0.z, b0.w, b1.x, b1.y, b1.z, b1.w};
#pragma unroll
            for (int i = 0; i < 8; i++)
#pragma unroll
                for (int j = 0; j < 8; j++) acc[i][j] += af[i] * bf[j];
        }
        __syncthreads();
    }

#pragma unroll
    for (int i = 0; i < 8; i++) {
        int r = rowBase + ty * 8 + i;
        if (r < M) {
#pragma unroll
            for (int j = 0; j < 8; j++) {
                int c = colBase + tx * 8 + j;
                if (c < N) C[(size_t)r * N + c] = alpha * acc[i][j];
            }
        }
    }
}

// ---------------- per-batch gram: out[i,j] = V[blk,i,:].V[blk,j,:] ----------------
__global__ __launch_bounds__(256) void gram_kernel(
    const float* __restrict__ V, float* __restrict__ out, int n)
{
    const float* Vb = V + (size_t)blockIdx.x * n * DN;
    __shared__ float sT[RN][65];
    float acc[6] = {0.f, 0.f, 0.f, 0.f, 0.f, 0.f};
    const int nn = n * n;
    for (int kt = 0; kt < DN; kt += 64) {
        for (int idx = threadIdx.x; idx < n * 64; idx += 256)
            sT[idx >> 6][idx & 63] = Vb[(size_t)(idx >> 6) * DN + kt + (idx & 63)];
        __syncthreads();
#pragma unroll
        for (int u = 0; u < 6; u++) {
            int o = threadIdx.x + u * 256;
            if (o < nn) {
                int i = o / n, j = o - i * n;
                float s = acc[u];
#pragma unroll
                for (int kk = 0; kk < 64; kk++) s += sT[i][kk] * sT[j][kk];
                acc[u] = s;
            }
        }
        __syncthreads();
    }
#pragma unroll
    for (int u = 0; u < 6; u++) {
        int o = threadIdx.x + u * 256;
        if (o < nn) out[(size_t)blockIdx.x * nn + o] = acc[u];
    }
}

// ---------------- fused per-pair path: p-mix -> relu MLP -> head softmax -> q ----------------
template <int NP, int LP>
__device__ __forceinline__ void do_path(
    const float* __restrict__ sP, int pstride,     // smem P[n*pstride + l]
    const float* __restrict__ Mrows,               // global LP x 1024
    const float* __restrict__ w2,                  // 4 x 1024
    const float* __restrict__ b1v,
    const float* __restrict__ b2v,
    float (*sM)[64], float (*sW2)[64], float* sB1,
    float (*sAcc)[HN], float (*sPA)[RN], float* sQ)
{
    const int tid  = threadIdx.x;
    const int nthr = blockDim.x;
    for (int i = tid; i < NP * HN; i += nthr) sAcc[i / HN][i % HN] = 0.f;

    const int rg  = tid >> 4;
    const int ee0 = (tid & 15) * 4;
    const int r0  = rg * 4;

    float acc[4][4];
#pragma unroll
    for (int i = 0; i < 4; i++)
#pragma unroll
        for (int h = 0; h < 4; h++) acc[i][h] = 0.f;

    for (int et = 0; et < DN; et += 64) {
        __syncthreads();  // protect sM/sW2/sB1 (and the sAcc zero on first iter)
        for (int idx = tid; idx < LP * 64; idx += nthr)
            sM[idx >> 6][idx & 63] = Mrows[(size_t)(idx >> 6) * DN + et + (idx & 63)];
        for (int idx = tid; idx < HN * 64; idx += nthr)
            sW2[idx >> 6][idx & 63] = w2[(size_t)(idx >> 6) * DN + et + (idx & 63)];
        if (tid < 64) sB1[tid] = b1v[et + tid];
        __syncthreads();

        if (r0 < NP) {
            float hv[4][4];
#pragma unroll
            for (int i = 0; i < 4; i++)
#pragma unroll
                for (int j = 0; j < 4; j++) hv[i][j] = sB1[ee0 + j];
#pragma unroll
            for (int l = 0; l < LP; l++) {
                const float4 m4 = *(const float4*)&sM[l][ee0];
#pragma unroll
                for (int i = 0; i < 4; i++) {
                    float p = (r0 + i < NP) ? sP[(r0 + i) * pstride + l] : 0.f;
                    hv[i][0] += p * m4.x; hv[i][1] += p * m4.y;
                    hv[i][2] += p * m4.z; hv[i][3] += p * m4.w;
                }
            }
#pragma unroll
            for (int j = 0; j < 4; j++) {
                float w0 = sW2[0][ee0 + j], w1 = sW2[1][ee0 + j];
                float w2v = sW2[2][ee0 + j], w3 = sW2[3][ee0 + j];
#pragma unroll
                for (int i = 0; i < 4; i++) {
                    float v = fmaxf(hv[i][j], 0.f);
                    acc[i][0] += v * w0; acc[i][1] += v * w1;
                    acc[i][2] += v * w2v; acc[i][3] += v * w3;
                }
            }
        }
    }
    __syncthreads();
    if (r0 < NP) {
#pragma unroll
        for (int i = 0; i < 4; i++)
            if (r0 + i < NP)
#pragma unroll
                for (int h = 0; h < 4; h++) atomicAdd(&sAcc[r0 + i][h], acc[i][h]);
    }
    __syncthreads();

    // per-head softmax over the NP positions
    if (tid < HN) {
        const int h = tid;
        float mx = -3.4e38f;
        for (int n = 0; n < NP; n++) {
            float s = sAcc[n][h] + b2v[h];
            sPA[h][n] = s;
            mx = fmaxf(mx, s);
        }
        float ssum = 0.f;
        for (int n = 0; n < NP; n++) { float e = expf(sPA[h][n] - mx); sPA[h][n] = e; ssum += e; }
        float inv = 1.f / ssum;
        for (int n = 0; n < NP; n++) sPA[h][n] *= inv;
    }
    __syncthreads();

    // q[l] = 1/4 * sum_h sum_n pA[h,n] * P[n,l]
    if (tid < LP) {
        float q = 0.f;
        for (int h = 0; h < HN; h++) {
            float qh = 0.f;
            for (int n = 0; n < NP; n++) qh += sPA[h][n] * sP[n * pstride + tid];
            q += qh;
        }
        sQ[tid] = q * 0.25f;
    }
    __syncthreads();
}

__global__ __launch_bounds__(160) void pair_kernel(
    const float* __restrict__ w2a, const float* __restrict__ b1a, const float* __restrict__ b2a,
    const float* __restrict__ w2b, const float* __restrict__ b1b, const float* __restrict__ b2b,
    float* __restrict__ out)
{
    const int b = blockIdx.x, a = blockIdx.y;
    const int tid = threadIdx.x;

    __shared__ float sS [LN][RN];
    __shared__ float sP1[LN][RN];   // softmax over r (rows l)
    __shared__ float sP2[RN][LN];   // softmax over l (rows r)
    __shared__ float sM [RN][64];
    __shared__ float sW2[HN][64];
    __shared__ float sB1[64];
    __shared__ float sAcc[RN][HN];
    __shared__ float sPA[HN][RN];
    __shared__ float sQA[LN];
    __shared__ float sQB[RN];
    __shared__ float sRed[3];

    for (int idx = tid; idx < LN * RN; idx += blockDim.x) {
        int l = idx / RN, r = idx - l * RN;
        sS[l][r] = g_S[(size_t)(b * LN + l) * (B1N * RN) + a * RN + r];
    }
    __syncthreads();

    if (tid < LN) {
        const int l = tid;
        float mx = -3.4e38f;
        for (int r = 0; r < RN; r++) mx = fmaxf(mx, sS[l][r]);
        float s = 0.f;
        for (int r = 0; r < RN; r++) { float e = expf(sS[l][r] - mx); sP1[l][r] = e; s += e; }
        float inv = 1.f / s;
        for (int r = 0; r < RN; r++) sP1[l][r] *= inv;
    }
    if (tid >= 32 && tid < 32 + RN) {
        const int r = tid - 32;
        float mx = -3.4e38f;
        for (int l = 0; l < LN; l++) mx = fmaxf(mx, sS[l][r]);
        float s = 0.f;
        for (int l = 0; l < LN; l++) { float e = expf(sS[l][r] - mx); sP2[r][l] = e; s += e; }
        float inv = 1.f / s;
        for (int l = 0; l < LN; l++) sP2[r][l] *= inv;
    }
    __syncthreads();

    // path A: co_v1 weights over v2 rows (uses p2, M2[b], w2a/b1a/b2a)
    do_path<RN, LN>(&sP2[0][0], LN, g_M2 + (size_t)b * LN * DN,
                    w2a, b1a, b2a, sM, sW2, sB1, sAcc, sPA, sQA);
    // path B: co_v2 weights over v1 rows (uses p1, M1[a], w2b/b1b/b2b)
    do_path<LN, RN>(&sP1[0][0], RN, g_M1 + (size_t)a * RN * DN,
                    w2b, b1b, b2b, sM, sW2, sB1, sAcc, sPA, sQB);

    // final: num = qB^T G qA ; norms via per-batch grams
    float pn = 0.f, p1n = 0.f, p2n = 0.f;
    for (int idx = tid; idx < RN * LN; idx += blockDim.x) {
        int l = idx / RN, r = idx - l * RN;   // r fastest -> coalesced G reads
        pn += sQB[r] * sQA[l] * g_G[(size_t)(b * LN + l) * (B1N * RN) + a * RN + r];
    }
    for (int idx = tid; idx < LN * LN; idx += blockDim.x)
        p1n += sQA[idx / LN] * sQA[idx % LN] * g_Gram2[(size_t)b * LN * LN + idx];
    for (int idx = tid; idx < RN * RN; idx += blockDim.x)
        p2n += sQB[idx / RN] * sQB[idx % RN] * g_Gram1[(size_t)a * RN * RN + idx];

    if (tid < 3) sRed[tid] = 0.f;
    __syncthreads();
    atomicAdd(&sRed[0], pn);
    atomicAdd(&sRed[1], p1n);
    atomicAdd(&sRed[2], p2n);
    __syncthreads();
    if (tid == 0) {
        float n1 = sqrtf(fmaxf(sRed[1], 0.f)) + 1e-8f;
        float n2 = sqrtf(fmaxf(sRed[2], 0.f)) + 1e-8f;
        out[a * B2N + b] = sRed[0] / (n1 * n2);
    }
}

// ---------------- launch ----------------
extern "C" void kernel_launch(void* const* d_in, const int* in_sizes, int n_in,
                              void* d_out, int out_size)
{
    const float* v1    = (const float*)d_in[0];
    const float* v2    = (const float*)d_in[1];
    const float* w_img = (const float*)d_in[2];
    const float* w_txt = (const float*)d_in[3];
    const float* w1a   = (const float*)d_in[4];
    const float* b1a   = (const float*)d_in[5];
    const float* w2a   = (const float*)d_in[6];
    const float* b2a   = (const float*)d_in[7];
    const float* w1b   = (const float*)d_in[8];
    const float* b1b   = (const float*)d_in[9];
    const float* w2b   = (const float*)d_in[10];
    const float* b2b   = (const float*)d_in[11];
    float* out = (float*)d_out;

    float *k1, *k2, *M1, *M2, *S, *G, *G1, *G2;
    cudaGetSymbolAddress((void**)&k1, g_k1);
    cudaGetSymbolAddress((void**)&k2, g_k2);
    cudaGetSymbolAddress((void**)&M1, g_M1);
    cudaGetSymbolAddress((void**)&M2, g_M2);
    cudaGetSymbolAddress((void**)&S,  g_S);
    cudaGetSymbolAddress((void**)&G,  g_G);
    cudaGetSymbolAddress((void**)&G1, g_Gram1);
    cudaGetSymbolAddress((void**)&G2, g_Gram2);

    const int MR = B1N * RN;   // 1728
    const int ML = B2N * LN;   // 1440
    dim3 blk(256);
    auto mkgrid = [](int M, int N) { return dim3((N + 127) / 128, (M + 127) / 128); };

    sgemm_nt<<<mkgrid(MR, DN), blk>>>(v1, w_img, k1, MR, DN, DN, 1.f);
    sgemm_nt<<<mkgrid(ML, DN), blk>>>(v2, w_txt, k2, ML, DN, DN, 1.f);
    sgemm_nt<<<mkgrid(MR, DN), blk>>>(v1, w1b,   M1, MR, DN, DN, 1.f);
    sgemm_nt<<<mkgrid(ML, DN), blk>>>(v2, w1a,   M2, ML, DN, DN, 1.f);
    sgemm_nt<<<mkgrid(ML, MR), blk>>>(k2, k1, S, ML, MR, DN, 0.03125f);  // 1/sqrt(1024)
    sgemm_nt<<<mkgrid(ML, MR), blk>>>(v2, v1, G, ML, MR, DN, 1.f);
    gram_kernel<<<B1N, 256>>>(v1, G1, RN);
    gram_kernel<<<B2N, 256>>>(v2, G2, LN);
    pair_kernel<<<dim3(B2N, B1N), 160>>>(w2a, b1a, b2a, w2b, b1b, b2b, out);
}

// round 5
// speedup vs baseline: 1.3466x; 1.3466x over previous
#include <cuda_runtime.h>
#include <cuda_bf16.h>
#include <math.h>

#define B1N 48
#define B2N 48
#define RN 36
#define LN 30
#define DN 1024
#define HN 4

#define MRTOT (B1N*RN)
#define MLTOT (B2N*LN)

// ---------------- scratch (static __device__, no allocs) ----------------
__device__ float g_k1[MRTOT*DN];
__device__ float g_k2[MLTOT*DN];
__device__ float g_M1[MRTOT*DN];
__device__ float g_M2[MLTOT*DN];
__device__ float g_S[MLTOT*MRTOT];
__device__ float g_G[MLTOT*MRTOT];
__device__ float g_Gram1[B1N*RN*RN];
__device__ float g_Gram2[B2N*LN*LN];

__device__ __nv_bfloat16 g_v1h[MRTOT*DN];
__device__ __nv_bfloat16 g_v1l[MRTOT*DN];
__device__ __nv_bfloat16 g_v2h[MLTOT*DN];
__device__ __nv_bfloat16 g_v2l[MLTOT*DN];
__device__ __nv_bfloat16 g_wih[DN*DN];
__device__ __nv_bfloat16 g_wil[DN*DN];
__device__ __nv_bfloat16 g_wth[DN*DN];
__device__ __nv_bfloat16 g_wtl[DN*DN];
__device__ __nv_bfloat16 g_w1ah[DN*DN];
__device__ __nv_bfloat16 g_w1al[DN*DN];
__device__ __nv_bfloat16 g_w1bh[DN*DN];
__device__ __nv_bfloat16 g_w1bl[DN*DN];
__device__ __nv_bfloat16 g_k1h[MRTOT*DN];
__device__ __nv_bfloat16 g_k1l[MRTOT*DN];
__device__ __nv_bfloat16 g_k2h[MLTOT*DN];
__device__ __nv_bfloat16 g_k2l[MLTOT*DN];

// ---------------- fp32 -> (hi, lo) bf16 split ----------------
// which: 0..5 external input x; 6 -> src g_k1; 7 -> src g_k2
__global__ void split_kernel(int which, const float* __restrict__ xin, int n4)
{
    const float* x = xin;
    __nv_bfloat16* hi = g_v1h;
    __nv_bfloat16* lo = g_v1l;
    if (which == 1) { hi = g_v2h;  lo = g_v2l;  }
    else if (which == 2) { hi = g_wih;  lo = g_wil;  }
    else if (which == 3) { hi = g_wth;  lo = g_wtl;  }
    else if (which == 4) { hi = g_w1ah; lo = g_w1al; }
    else if (which == 5) { hi = g_w1bh; lo = g_w1bl; }
    else if (which == 6) { x = g_k1; hi = g_k1h; lo = g_k1l; }
    else if (which == 7) { x = g_k2; hi = g_k2h; lo = g_k2l; }

    int i = blockIdx.x * blockDim.x + threadIdx.x;
    if (i >= n4) return;
    float4 v = ((const float4*)x)[i];
    __nv_bfloat16 h0 = __float2bfloat16(v.x);
    __nv_bfloat16 h1 = __float2bfloat16(v.y);
    __nv_bfloat16 h2 = __float2bfloat16(v.z);
    __nv_bfloat16 h3 = __float2bfloat16(v.w);
    __nv_bfloat162 ph0;
    ph0.x = h0;
    ph0.y = h1;
    __nv_bfloat162 ph1;
    ph1.x = h2;
    ph1.y = h3;
    ((__nv_bfloat162*)hi)[2*i]   = ph0;
    ((__nv_bfloat162*)hi)[2*i+1] = ph1;
    __nv_bfloat162 pl0;
    pl0.x = __float2bfloat16(v.x - __bfloat162float(h0));
    pl0.y = __float2bfloat16(v.y - __bfloat162float(h1));
    __nv_bfloat162 pl1;
    pl1.x = __float2bfloat16(v.z - __bfloat162float(h2));
    pl1.y = __float2bfloat16(v.w - __bfloat162float(h3));
    ((__nv_bfloat162*)lo)[2*i]   = pl0;
    ((__nv_bfloat162*)lo)[2*i+1] = pl1;
}

// ---------------- tensor-core NT GEMM with split-bf16 compensation ----------------
#define BM 128
#define BN 128
#define BK 32
#define SSTR 40

__device__ __forceinline__ unsigned smem_u32(const void* p) {
    return (unsigned)__cvta_generic_to_shared(p);
}
__device__ __forceinline__ void ldm_x4(unsigned* r, unsigned addr) {
    asm volatile("ldmatrix.sync.aligned.m8n8.x4.shared.b16 {%0,%1,%2,%3}, [%4];"
        : "=r"(r[0]), "=r"(r[1]), "=r"(r[2]), "=r"(r[3]) : "r"(addr));
}
__device__ __forceinline__ void mma16816(float* c, const unsigned* a,
                                         unsigned b0, unsigned b1) {
    asm volatile(
        "mma.sync.aligned.m16n8k16.row.col.f32.bf16.bf16.f32 "
        "{%0,%1,%2,%3}, {%4,%5,%6,%7}, {%8,%9}, {%0,%1,%2,%3};\n"
        : "+f"(c[0]), "+f"(c[1]), "+f"(c[2]), "+f"(c[3])
        : "r"(a[0]), "r"(a[1]), "r"(a[2]), "r"(a[3]), "r"(b0), "r"(b1));
}

// which: 0 k1 = v1*w_img ; 1 k2 = v2*w_txt ; 2 M1 = v1*w1b ; 3 M2 = v2*w1a ;
//        4 G = v2*v1^T ; 5 S = k2*k1^T * 1/32
__global__ __launch_bounds__(256, 1) void mma_gemm_nt(int which)
{
    const __nv_bfloat16* Ahi = g_v1h;
    const __nv_bfloat16* Alo = g_v1l;
    const __nv_bfloat16* Bhi = g_wih;
    const __nv_bfloat16* Blo = g_wil;
    float* C = g_k1;
    int M = MRTOT;
    int N = DN;
    float alpha = 1.f;
    if (which == 1) {
        Ahi = g_v2h; Alo = g_v2l; Bhi = g_wth; Blo = g_wtl;
        C = g_k2; M = MLTOT; N = DN; alpha = 1.f;
    } else if (which == 2) {
        Ahi = g_v1h; Alo = g_v1l; Bhi = g_w1bh; Blo = g_w1bl;
        C = g_M1; M = MRTOT; N = DN; alpha = 1.f;
    } else if (which == 3) {
        Ahi = g_v2h; Alo = g_v2l; Bhi = g_w1ah; Blo = g_w1al;
        C = g_M2; M = MLTOT; N = DN; alpha = 1.f;
    } else if (which == 4) {
        Ahi = g_v2h; Alo = g_v2l; Bhi = g_v1h; Blo = g_v1l;
        C = g_G; M = MLTOT; N = MRTOT; alpha = 1.f;
    } else if (which == 5) {
        Ahi = g_k2h; Alo = g_k2l; Bhi = g_k1h; Blo = g_k1l;
        C = g_S; M = MLTOT; N = MRTOT; alpha = 0.03125f;
    }
    const int K = DN;

    __shared__ alignas(16) __nv_bfloat16 sAh[BM][SSTR];
    __shared__ alignas(16) __nv_bfloat16 sAl[BM][SSTR];
    __shared__ alignas(16) __nv_bfloat16 sBh[BN][SSTR];
    __shared__ alignas(16) __nv_bfloat16 sBl[BN][SSTR];

    const int tid  = threadIdx.x;
    const int warp = tid >> 5;
    const int lane = tid & 31;
    const int wm = (warp >> 2) * 64;
    const int wn = (warp & 3) * 32;
    const int rowBase = blockIdx.y * BM;
    const int colBase = blockIdx.x * BN;

    float acc[4][4][4];
#pragma unroll
    for (int i = 0; i < 4; i++) {
#pragma unroll
        for (int j = 0; j < 4; j++) {
#pragma unroll
            for (int q = 0; q < 4; q++) {
                acc[i][j][q] = 0.f;
            }
        }
    }

    int srow[2];
    int scol[2];
    bool aok[2];
    bool bok[2];
#pragma unroll
    for (int it = 0; it < 2; it++) {
        int idx = tid + it * 256;
        srow[it] = idx >> 2;
        scol[it] = (idx & 3) * 8;
        aok[it] = (rowBase + srow[it]) < M;
        bok[it] = (colBase + srow[it]) < N;
    }

    uint4 rAh[2];
    uint4 rAl[2];
    uint4 rBh[2];
    uint4 rBl[2];
    const uint4 z4 = make_uint4(0u, 0u, 0u, 0u);

#pragma unroll
    for (int it = 0; it < 2; it++) {
        size_t ao = (size_t)(rowBase + srow[it]) * K + scol[it];
        size_t bo = (size_t)(colBase + srow[it]) * K + scol[it];
        rAh[it] = aok[it] ? *(const uint4*)&Ahi[ao] : z4;
        rAl[it] = aok[it] ? *(const uint4*)&Alo[ao] : z4;
        rBh[it] = bok[it] ? *(const uint4*)&Bhi[bo] : z4;
        rBl[it] = bok[it] ? *(const uint4*)&Blo[bo] : z4;
    }

    const int lr = lane & 15;
    const int lc = lane >> 4;

    for (int kt = 0; kt < K; kt += BK) {
#pragma unroll
        for (int it = 0; it < 2; it++) {
            *(uint4*)&sAh[srow[it]][scol[it]] = rAh[it];
            *(uint4*)&sAl[srow[it]][scol[it]] = rAl[it];
            *(uint4*)&sBh[srow[it]][scol[it]] = rBh[it];
            *(uint4*)&sBl[srow[it]][scol[it]] = rBl[it];
        }
        __syncthreads();

        if (kt + BK < K) {
#pragma unroll
            for (int it = 0; it < 2; it++) {
                size_t ao = (size_t)(rowBase + srow[it]) * K + kt + BK + scol[it];
                size_t bo = (size_t)(colBase + srow[it]) * K + kt + BK + scol[it];
                rAh[it] = aok[it] ? *(const uint4*)&Ahi[ao] : z4;
                rAl[it] = aok[it] ? *(const uint4*)&Alo[ao] : z4;
                rBh[it] = bok[it] ? *(const uint4*)&Bhi[bo] : z4;
                rBl[it] = bok[it] ? *(const uint4*)&Blo[bo] : z4;
            }
        }

#pragma unroll
        for (int kk = 0; kk < 2; kk++) {
            const int k0 = kk * 16;
            unsigned ah[4][4];
            unsigned al[4][4];
            unsigned bh[2][4];
            unsigned bl[2][4];
#pragma unroll
            for (int mi = 0; mi < 4; mi++) {
                ldm_x4(ah[mi], smem_u32(&sAh[wm + 16*mi + lr][k0 + 8*lc]));
                ldm_x4(al[mi], smem_u32(&sAl[wm + 16*mi + lr][k0 + 8*lc]));
            }
#pragma unroll
            for (int j = 0; j < 2; j++) {
                ldm_x4(bh[j], smem_u32(&sBh[wn + 16*j + lr][k0 + 8*lc]));
                ldm_x4(bl[j], smem_u32(&sBl[wn + 16*j + lr][k0 + 8*lc]));
            }
#pragma unroll
            for (int mi = 0; mi < 4; mi++) {
#pragma unroll
                for (int nj = 0; nj < 4; nj++) {
                    const int j = nj >> 1;
                    const int s = nj & 1;
                    mma16816(acc[mi][nj], ah[mi], bh[j][s], bh[j][s + 2]);
                    mma16816(acc[mi][nj], ah[mi], bl[j][s], bl[j][s + 2]);
                    mma16816(acc[mi][nj], al[mi], bh[j][s], bh[j][s + 2]);
                }
            }
        }
        __syncthreads();
    }

    const int er = lane >> 2;
    const int ec = (lane & 3) * 2;
#pragma unroll
    for (int mi = 0; mi < 4; mi++) {
        int r0 = rowBase + wm + 16*mi + er;
        int r1 = r0 + 8;
#pragma unroll
        for (int nj = 0; nj < 4; nj++) {
            int c0 = colBase + wn + 8*nj + ec;
            if (c0 < N) {
                if (r0 < M) {
                    float2 o0;
                    o0.x = alpha * acc[mi][nj][0];
                    o0.y = alpha * acc[mi][nj][1];
                    *(float2*)&C[(size_t)r0 * N + c0] = o0;
                }
                if (r1 < M) {
                    float2 o1;
                    o1.x = alpha * acc[mi][nj][2];
                    o1.y = alpha * acc[mi][nj][3];
                    *(float2*)&C[(size_t)r1 * N + c0] = o1;
                }
            }
        }
    }
}

// ---------------- per-batch gram: whichOut 0 -> g_Gram1, 1 -> g_Gram2 ----------------
__global__ __launch_bounds__(256) void gram_kernel(
    const float* __restrict__ V, int whichOut, int n)
{
    float* out = (whichOut == 0) ? g_Gram1 : g_Gram2;
    const float* Vb = V + (size_t)blockIdx.x * n * DN;
    __shared__ float sT[RN][65];
    float acc[6] = {0.f, 0.f, 0.f, 0.f, 0.f, 0.f};
    const int nn = n * n;
    for (int kt = 0; kt < DN; kt += 64) {
        for (int idx = threadIdx.x; idx < n * 64; idx += 256) {
            sT[idx >> 6][idx & 63] = Vb[(size_t)(idx >> 6) * DN + kt + (idx & 63)];
        }
        __syncthreads();
#pragma unroll
        for (int u = 0; u < 6; u++) {
            int o = threadIdx.x + u * 256;
            if (o < nn) {
                int i = o / n;
                int j = o - i * n;
                float s = acc[u];
#pragma unroll
                for (int kk = 0; kk < 64; kk++) {
                    s += sT[i][kk] * sT[j][kk];
                }
                acc[u] = s;
            }
        }
        __syncthreads();
    }
#pragma unroll
    for (int u = 0; u < 6; u++) {
        int o = threadIdx.x + u * 256;
        if (o < nn) {
            out[(size_t)blockIdx.x * nn + o] = acc[u];
        }
    }
}

// ---------------- fused per-pair path ----------------
template <int NP, int LP>
__device__ __forceinline__ void do_path(
    const float* __restrict__ sP, int pstride,
    const float* __restrict__ Mrows,
    const float* __restrict__ w2,
    const float* __restrict__ b1v,
    const float* __restrict__ b2v,
    float (*sM)[64], float (*sW2)[64], float* sB1,
    float (*sAcc)[HN], float (*sPA)[RN], float* sQ)
{
    const int tid  = threadIdx.x;
    const int nthr = blockDim.x;
    for (int i = tid; i < NP * HN; i += nthr) {
        sAcc[i / HN][i % HN] = 0.f;
    }

    const int rg  = tid >> 4;
    const int ee0 = (tid & 15) * 4;
    const int r0  = rg * 4;

    float acc[4][4];
#pragma unroll
    for (int i = 0; i < 4; i++) {
#pragma unroll
        for (int h = 0; h < 4; h++) {
            acc[i][h] = 0.f;
        }
    }

    for (int et = 0; et < DN; et += 64) {
        __syncthreads();
        for (int idx = tid; idx < LP * 64; idx += nthr) {
            sM[idx >> 6][idx & 63] = Mrows[(size_t)(idx >> 6) * DN + et + (idx & 63)];
        }
        for (int idx = tid; idx < HN * 64; idx += nthr) {
            sW2[idx >> 6][idx & 63] = w2[(size_t)(idx >> 6) * DN + et + (idx & 63)];
        }
        if (tid < 64) {
            sB1[tid] = b1v[et + tid];
        }
        __syncthreads();

        if (r0 < NP) {
            float hv[4][4];
#pragma unroll
            for (int i = 0; i < 4; i++) {
#pragma unroll
                for (int j = 0; j < 4; j++) {
                    hv[i][j] = sB1[ee0 + j];
                }
            }
#pragma unroll
            for (int l = 0; l < LP; l++) {
                const float4 m4 = *(const float4*)&sM[l][ee0];
#pragma unroll
                for (int i = 0; i < 4; i++) {
                    float p = (r0 + i < NP) ? sP[(r0 + i) * pstride + l] : 0.f;
                    hv[i][0] += p * m4.x;
                    hv[i][1] += p * m4.y;
                    hv[i][2] += p * m4.z;
                    hv[i][3] += p * m4.w;
                }
            }
#pragma unroll
            for (int j = 0; j < 4; j++) {
                float u0 = sW2[0][ee0 + j];
                float u1 = sW2[1][ee0 + j];
                float u2 = sW2[2][ee0 + j];
                float u3 = sW2[3][ee0 + j];
#pragma unroll
                for (int i = 0; i < 4; i++) {
                    float v = fmaxf(hv[i][j], 0.f);
                    acc[i][0] += v * u0;
                    acc[i][1] += v * u1;
                    acc[i][2] += v * u2;
                    acc[i][3] += v * u3;
                }
            }
        }
    }
    __syncthreads();
    if (r0 < NP) {
#pragma unroll
        for (int i = 0; i < 4; i++) {
            if (r0 + i < NP) {
#pragma unroll
                for (int h = 0; h < 4; h++) {
                    atomicAdd(&sAcc[r0 + i][h], acc[i][h]);
                }
            }
        }
    }
    __syncthreads();

    if (tid < HN) {
        const int h = tid;
        float mx = -3.4e38f;
        for (int n = 0; n < NP; n++) {
            float s = sAcc[n][h] + b2v[h];
            sPA[h][n] = s;
            mx = fmaxf(mx, s);
        }
        float ssum = 0.f;
        for (int n = 0; n < NP; n++) {
            float e = expf(sPA[h][n] - mx);
            sPA[h][n] = e;
            ssum += e;
        }
        float inv = 1.f / ssum;
        for (int n = 0; n < NP; n++) {
            sPA[h][n] *= inv;
        }
    }
    __syncthreads();

    if (tid < LP) {
        float q = 0.f;
        for (int h = 0; h < HN; h++) {
            float qh = 0.f;
            for (int n = 0; n < NP; n++) {
                qh += sPA[h][n] * sP[n * pstride + tid];
            }
            q += qh;
        }
        sQ[tid] = q * 0.25f;
    }
    __syncthreads();
}

__global__ __launch_bounds__(160) void pair_kernel(
    const float* __restrict__ w2a, const float* __restrict__ b1a, const float* __restrict__ b2a,
    const float* __restrict__ w2b, const float* __restrict__ b1b, const float* __restrict__ b2b,
    float* __restrict__ out)
{
    const int b = blockIdx.x;
    const int a = blockIdx.y;
    const int tid = threadIdx.x;

    __shared__ float sS[LN][RN];
    __shared__ float sP1[LN][RN];
    __shared__ float sP2[RN][LN];
    __shared__ float sM[RN][64];
    __shared__ float sW2[HN][64];
    __shared__ float sB1[64];
    __shared__ float sAcc[RN][HN];
    __shared__ float sPA[HN][RN];
    __shared__ float sQA[LN];
    __shared__ float sQB[RN];
    __shared__ float sRed[3];

    for (int idx = tid; idx < LN * RN; idx += blockDim.x) {
        int l = idx / RN;
        int r = idx - l * RN;
        sS[l][r] = g_S[(size_t)(b * LN + l) * (B1N * RN) + a * RN + r];
    }
    __syncthreads();

    if (tid < LN) {
        const int l = tid;
        float mx = -3.4e38f;
        for (int r = 0; r < RN; r++) {
            mx = fmaxf(mx, sS[l][r]);
        }
        float s = 0.f;
        for (int r = 0; r < RN; r++) {
            float e = expf(sS[l][r] - mx);
            sP1[l][r] = e;
            s += e;
        }
        float inv = 1.f / s;
        for (int r = 0; r < RN; r++) {
            sP1[l][r] *= inv;
        }
    }
    if (tid >= 32 && tid < 32 + RN) {
        const int r = tid - 32;
        float mx = -3.4e38f;
        for (int l = 0; l < LN; l++) {
            mx = fmaxf(mx, sS[l][r]);
        }
        float s = 0.f;
        for (int l = 0; l < LN; l++) {
            float e = expf(sS[l][r] - mx);
            sP2[r][l] = e;
            s += e;
        }
        float inv = 1.f / s;
        for (int l = 0; l < LN; l++) {
            sP2[r][l] *= inv;
        }
    }
    __syncthreads();

    do_path<RN, LN>(&sP2[0][0], LN, g_M2 + (size_t)b * LN * DN,
                    w2a, b1a, b2a, sM, sW2, sB1, sAcc, sPA, sQA);
    do_path<LN, RN>(&sP1[0][0], RN, g_M1 + (size_t)a * RN * DN,
                    w2b, b1b, b2b, sM, sW2, sB1, sAcc, sPA, sQB);

    float pn = 0.f;
    float p1n = 0.f;
    float p2n = 0.f;
    for (int idx = tid; idx < RN * LN; idx += blockDim.x) {
        int l = idx / RN;
        int r = idx - l * RN;
        pn += sQB[r] * sQA[l] * g_G[(size_t)(b * LN + l) * (B1N * RN) + a * RN + r];
    }
    for (int idx = tid; idx < LN * LN; idx += blockDim.x) {
        p1n += sQA[idx / LN] * sQA[idx % LN] * g_Gram2[(size_t)b * LN * LN + idx];
    }
    for (int idx = tid; idx < RN * RN; idx += blockDim.x) {
        p2n += sQB[idx / RN] * sQB[idx % RN] * g_Gram1[(size_t)a * RN * RN + idx];
    }

    if (tid < 3) {
        sRed[tid] = 0.f;
    }
    __syncthreads();
    atomicAdd(&sRed[0], pn);
    atomicAdd(&sRed[1], p1n);
    atomicAdd(&sRed[2], p2n);
    __syncthreads();
    if (tid == 0) {
        float n1 = sqrtf(fmaxf(sRed[1], 0.f)) + 1e-8f;
        float n2 = sqrtf(fmaxf(sRed[2], 0.f)) + 1e-8f;
        out[a * B2N + b] = sRed[0] / (n1 * n2);
    }
}

// ---------------- launch ----------------
extern "C" void kernel_launch(void* const* d_in, const int* in_sizes, int n_in,
                              void* d_out, int out_size)
{
    const float* v1    = (const float*)d_in[0];
    const float* v2    = (const float*)d_in[1];
    const float* w_img = (const float*)d_in[2];
    const float* w_txt = (const float*)d_in[3];
    const float* w1a   = (const float*)d_in[4];
    const float* b1a   = (const float*)d_in[5];
    const float* w2a   = (const float*)d_in[6];
    const float* b2a   = (const float*)d_in[7];
    const float* w1b   = (const float*)d_in[8];
    const float* b1b   = (const float*)d_in[9];
    const float* w2b   = (const float*)d_in[10];
    const float* b2b   = (const float*)d_in[11];
    float* out = (float*)d_out;

    const int n4R = (MRTOT * DN) / 4;
    const int n4L = (MLTOT * DN) / 4;
    const int n4W = (DN * DN) / 4;

    split_kernel<<<(n4R + 255) / 256, 256>>>(0, v1, n4R);
    split_kernel<<<(n4L + 255) / 256, 256>>>(1, v2, n4L);
    split_kernel<<<(n4W + 255) / 256, 256>>>(2, w_img, n4W);
    split_kernel<<<(n4W + 255) / 256, 256>>>(3, w_txt, n4W);
    split_kernel<<<(n4W + 255) / 256, 256>>>(4, w1a, n4W);
    split_kernel<<<(n4W + 255) / 256, 256>>>(5, w1b, n4W);

    dim3 gridKR((DN + BN - 1) / BN, (MRTOT + BM - 1) / BM);
    dim3 gridKL((DN + BN - 1) / BN, (MLTOT + BM - 1) / BM);
    dim3 gridSG((MRTOT + BN - 1) / BN, (MLTOT + BM - 1) / BM);

    mma_gemm_nt<<<gridKR, 256>>>(0);
    mma_gemm_nt<<<gridKL, 256>>>(1);
    mma_gemm_nt<<<gridKR, 256>>>(2);
    mma_gemm_nt<<<gridKL, 256>>>(3);
    mma_gemm_nt<<<gridSG, 256>>>(4);

    split_kernel<<<(n4R + 255) / 256, 256>>>(6, v1, n4R);
    split_kernel<<<(n4L + 255) / 256, 256>>>(7, v2, n4L);
    mma_gemm_nt<<<gridSG, 256>>>(5);

    gram_kernel<<<B1N, 256>>>(v1, 0, RN);
    gram_kernel<<<B2N, 256>>>(v2, 1, LN);
    pair_kernel<<<dim3(B2N, B1N), 160>>>(w2a, b1a, b2a, w2b, b1b, b2b, out);
}